// round 1
// baseline (speedup 1.0000x reference)
#include <cuda_runtime.h>
#include <math.h>

#define TT 2048
#define HDIM 2048
#define NHEADS 32
#define NKVH 8
#define HEADD 64
#define SWIN 128
#define QKVD 3072   // HEADD * (NHEADS + 2*NKVH)

// ---------------- scratch (device globals; no allocation allowed) ----------------
__device__ float g_normed[TT * HDIM];
__device__ float g_qkv[(size_t)TT * QKVD];
__device__ float g_attn[TT * HDIM];

// ---------------- RMSNorm ----------------
__global__ void rmsnorm_kernel(const float* __restrict__ x,
                               const float* __restrict__ scale) {
    int t = blockIdx.x;
    const float* row = x + (size_t)t * HDIM;
    float ss = 0.f;
    for (int i = threadIdx.x; i < HDIM; i += blockDim.x) {
        float v = row[i];
        ss += v * v;
    }
    __shared__ float sh[9];
    #pragma unroll
    for (int o = 16; o; o >>= 1) ss += __shfl_xor_sync(0xffffffffu, ss, o);
    int lane = threadIdx.x & 31, wid = threadIdx.x >> 5;
    if (lane == 0) sh[wid] = ss;
    __syncthreads();
    if (threadIdx.x == 0) {
        float s = 0.f;
        for (int i = 0; i < (int)(blockDim.x >> 5); i++) s += sh[i];
        sh[8] = rsqrtf(s / (float)HDIM + 1e-5f);
    }
    __syncthreads();
    float inv = sh[8];
    for (int i = threadIdx.x; i < HDIM; i += blockDim.x)
        g_normed[(size_t)t * HDIM + i] = row[i] * inv * scale[i];
}

// ---------------- fp32 GEMM: C[M,N] = A[M,K] @ B[K,N] + bias (+ resid) ----------------
// BM=BN=128, BK=8, 256 threads, 8x8 per-thread microtile.
// Dims must be multiples of the tile (true here: M=2048, N in {3072,2048}, K=2048).
__global__ void gemm128(const float* __restrict__ A, const float* __restrict__ B,
                        const float* __restrict__ bias, const float* __restrict__ resid,
                        float* __restrict__ C, int N, int K) {
    __shared__ float As[8][128];
    __shared__ float Bs[8][128];
    const int m0 = blockIdx.y * 128;
    const int n0 = blockIdx.x * 128;
    const int tid = threadIdx.x;            // 256
    const int tx = tid & 15;                // 0..15
    const int ty = tid >> 4;                // 0..15

    float acc[8][8];
    #pragma unroll
    for (int i = 0; i < 8; i++)
        #pragma unroll
        for (int j = 0; j < 8; j++) acc[i][j] = 0.f;

    const float* Ab = A + (size_t)m0 * K;
    const float* Bb = B + n0;
    const int arow = tid >> 1;              // 0..127
    const int acol = (tid & 1) * 4;         // 0 or 4

    for (int k0 = 0; k0 < K; k0 += 8) {
        float4 av = *(const float4*)(Ab + (size_t)arow * K + k0 + acol);
        As[acol + 0][arow] = av.x;
        As[acol + 1][arow] = av.y;
        As[acol + 2][arow] = av.z;
        As[acol + 3][arow] = av.w;
        #pragma unroll
        for (int i = 0; i < 4; i++) {
            int idx = tid + 256 * i;
            int kk = idx >> 7, nn = idx & 127;
            Bs[kk][nn] = Bb[(size_t)(k0 + kk) * N + nn];
        }
        __syncthreads();
        #pragma unroll
        for (int k = 0; k < 8; k++) {
            float a[8], b[8];
            *(float4*)(a)     = *(const float4*)&As[k][ty * 8];
            *(float4*)(a + 4) = *(const float4*)&As[k][ty * 8 + 4];
            *(float4*)(b)     = *(const float4*)&Bs[k][tx * 8];
            *(float4*)(b + 4) = *(const float4*)&Bs[k][tx * 8 + 4];
            #pragma unroll
            for (int i = 0; i < 8; i++)
                #pragma unroll
                for (int j = 0; j < 8; j++) acc[i][j] += a[i] * b[j];
        }
        __syncthreads();
    }

    #pragma unroll
    for (int i = 0; i < 8; i++) {
        int m = m0 + ty * 8 + i;
        #pragma unroll
        for (int j = 0; j < 8; j++) {
            int n = n0 + tx * 8 + j;
            float v = acc[i][j] + bias[n];
            if (resid) v += resid[(size_t)m * N + n];
            C[(size_t)m * N + n] = v;
        }
    }
}

// ---------------- RoPE (in-place on g_qkv: 32 q-heads + 8 k-heads, contiguous) ----------------
__global__ void rope_kernel(const float* __restrict__ cos_t,
                            const float* __restrict__ sin_t) {
    int t = blockIdx.x;
    const float* c = cos_t + t * 32;
    const float* s = sin_t + t * 32;
    float* rowbase = g_qkv + (size_t)t * QKVD;
    // 40 head-vectors of 64 (q: heads 0..31 at offset 0..2047, k: heads 32..39 at 2048..2559)
    for (int i = threadIdx.x; i < 40 * 32; i += blockDim.x) {
        int head = i >> 5, r = i & 31;
        float* base = rowbase + head * HEADD;
        float x1 = base[r], x2 = base[r + 32];
        float cv = c[r], sv = s[r];
        base[r]      = x1 * cv - x2 * sv;
        base[r + 32] = x2 * cv + x1 * sv;
    }
}

// ---------------- sliding-window GQA attention with sink ----------------
// one block (128 threads) per (query q, head h)
__global__ void attn_kernel(const float* __restrict__ sinks) {
    const int q = blockIdx.x;
    const int h = blockIdx.y;
    const int n = h >> 2;                   // kv head
    const int tid = threadIdx.x;

    __shared__ float qv[HEADD];
    __shared__ float sc[SWIN + 1];
    __shared__ float red[8];

    const float* qkv = g_qkv;
    if (tid < HEADD) qv[tid] = qkv[(size_t)q * QKVD + h * HEADD + tid];
    __syncthreads();

    const int k0 = (q - SWIN > 0) ? (q - SWIN) : 0;
    const int cnt = q - k0 + 1;             // <= 129

    float lmax = -INFINITY;
    for (int j = tid; j < cnt; j += 128) {
        const float* krow = qkv + (size_t)(k0 + j) * QKVD + NHEADS * HEADD + n * HEADD;
        float s = 0.f;
        #pragma unroll
        for (int d = 0; d < HEADD; d++) s += qv[d] * krow[d];
        s *= 0.125f;                        // 1/sqrt(64)
        sc[j] = s;
        lmax = fmaxf(lmax, s);
    }
    #pragma unroll
    for (int o = 16; o; o >>= 1) lmax = fmaxf(lmax, __shfl_xor_sync(0xffffffffu, lmax, o));
    int lane = tid & 31, wid = tid >> 5;
    if (lane == 0) red[wid] = lmax;
    __syncthreads();
    if (tid == 0) {
        float m = sinks[h];
        for (int i = 0; i < 4; i++) m = fmaxf(m, red[i]);
        red[4] = m;
    }
    __syncthreads();
    const float mx = red[4];

    float lsum = 0.f;
    for (int j = tid; j < cnt; j += 128) {
        float e = expf(sc[j] - mx);
        sc[j] = e;
        lsum += e;
    }
    #pragma unroll
    for (int o = 16; o; o >>= 1) lsum += __shfl_xor_sync(0xffffffffu, lsum, o);
    if (lane == 0) red[wid] = lsum;
    __syncthreads();
    if (tid == 0) {
        float s = red[0] + red[1] + red[2] + red[3];
        s += expf(sinks[h] - mx);           // sink column in denominator
        red[5] = 1.f / s;
    }
    __syncthreads();
    const float inv = red[5];

    if (tid < HEADD) {
        float acc = 0.f;
        const float* vbase = qkv + (size_t)k0 * QKVD + (NHEADS + NKVH) * HEADD + n * HEADD + tid;
        for (int j = 0; j < cnt; j++)
            acc += sc[j] * vbase[(size_t)j * QKVD];
        g_attn[(size_t)q * HDIM + h * HEADD + tid] = acc * inv;
    }
}

// ---------------- launch ----------------
extern "C" void kernel_launch(void* const* d_in, const int* in_sizes, int n_in,
                              void* d_out, int out_size) {
    const float* x          = (const float*)d_in[0];
    const float* scale      = (const float*)d_in[1];
    const float* sinks      = (const float*)d_in[2];
    const float* qkv_kernel = (const float*)d_in[3];
    const float* qkv_bias   = (const float*)d_in[4];
    const float* out_kernel = (const float*)d_in[5];
    const float* out_bias   = (const float*)d_in[6];
    const float* cos_t      = (const float*)d_in[7];
    const float* sin_t      = (const float*)d_in[8];
    // d_in[9] = mask: unused (sliding window applied structurally)
    float* out = (float*)d_out;

    void *p_normed = nullptr, *p_qkv = nullptr, *p_attn = nullptr;
    cudaGetSymbolAddress(&p_normed, g_normed);
    cudaGetSymbolAddress(&p_qkv, g_qkv);
    cudaGetSymbolAddress(&p_attn, g_attn);

    rmsnorm_kernel<<<TT, 256>>>(x, scale);

    // QKV: [2048,2048] @ [2048,3072]
    gemm128<<<dim3(QKVD / 128, TT / 128), 256>>>(
        (const float*)p_normed, qkv_kernel, qkv_bias, nullptr,
        (float*)p_qkv, QKVD, HDIM);

    rope_kernel<<<TT, 256>>>(cos_t, sin_t);

    attn_kernel<<<dim3(TT, NHEADS), 128>>>(sinks);

    // out-proj + residual: [2048,2048] @ [2048,2048] + x
    gemm128<<<dim3(HDIM / 128, TT / 128), 256>>>(
        (const float*)p_attn, out_kernel, out_bias, x,
        out, HDIM, HDIM);
}

// round 3
// speedup vs baseline: 2.9448x; 2.9448x over previous
#include <cuda_runtime.h>
#include <math.h>

#define TT 2048
#define HDIM 2048
#define NHEADS 32
#define NKVH 8
#define HEADD 64
#define SWIN 128
#define QKVD 3072   // HEADD * (NHEADS + 2*NKVH)

// ---------------- scratch (device globals; no allocation allowed) ----------------
__device__ float g_normed[TT * HDIM];
__device__ float g_qkv[(size_t)TT * QKVD];
__device__ float g_attn[TT * HDIM];

// ---------------- RMSNorm ----------------
__global__ void rmsnorm_kernel(const float* __restrict__ x,
                               const float* __restrict__ scale) {
    int t = blockIdx.x;
    const float* row = x + (size_t)t * HDIM;
    float ss = 0.f;
    for (int i = threadIdx.x; i < HDIM; i += blockDim.x) {
        float v = row[i];
        ss += v * v;
    }
    __shared__ float sh[9];
    #pragma unroll
    for (int o = 16; o; o >>= 1) ss += __shfl_xor_sync(0xffffffffu, ss, o);
    int lane = threadIdx.x & 31, wid = threadIdx.x >> 5;
    if (lane == 0) sh[wid] = ss;
    __syncthreads();
    if (threadIdx.x == 0) {
        float s = 0.f;
        for (int i = 0; i < (int)(blockDim.x >> 5); i++) s += sh[i];
        sh[8] = rsqrtf(s / (float)HDIM + 1e-5f);
    }
    __syncthreads();
    float inv = sh[8];
    for (int i = threadIdx.x; i < HDIM; i += blockDim.x)
        g_normed[(size_t)t * HDIM + i] = row[i] * inv * scale[i];
}

// ---------------- TF32 tensor-core GEMM (3xTF32 compensated, ~fp32 accuracy) ----
// C[M,N] = A[M,K] @ B[K,N] + bias (+ resid). BM=BN=128, BK=16, 256 threads.
// Warp grid 2x4, warp tile 64x32, mma.sync.m16n8k8 tf32.

__device__ __forceinline__ void split32(float f, unsigned& hi, unsigned& lo) {
    asm("cvt.rna.tf32.f32 %0, %1;" : "=r"(hi) : "f"(f));
    float r = f - __uint_as_float(hi);
    asm("cvt.rna.tf32.f32 %0, %1;" : "=r"(lo) : "f"(r));
}

#define MMA8(d, a, b) asm volatile( \
  "mma.sync.aligned.m16n8k8.row.col.f32.tf32.tf32.f32 " \
  "{%0,%1,%2,%3},{%4,%5,%6,%7},{%8,%9},{%0,%1,%2,%3};\n" \
  : "+f"((d)[0]), "+f"((d)[1]), "+f"((d)[2]), "+f"((d)[3]) \
  : "r"((a)[0]), "r"((a)[1]), "r"((a)[2]), "r"((a)[3]), \
    "r"((b)[0]), "r"((b)[1]))

__global__ __launch_bounds__(256, 1) void gemm_tf32(
    const float* __restrict__ A, const float* __restrict__ B,
    const float* __restrict__ bias, const float* __restrict__ resid,
    float* __restrict__ C, int N, int K)
{
    __shared__ float As[2][128][20];   // [m][k], pad 4 -> conflict-free frag loads
    __shared__ float Bs[2][16][136];   // [k][n], pad 8 -> conflict-free frag loads
    const int tid  = threadIdx.x;
    const int lane = tid & 31;
    const int wid  = tid >> 5;
    const int grp  = lane >> 2;        // 0..7
    const int qid  = lane & 3;         // 0..3
    const int wm   = (wid >> 2) * 64;  // 0 / 64
    const int wn   = (wid & 3) * 32;   // 0..96
    const int m0 = blockIdx.y * 128;
    const int n0 = blockIdx.x * 128;

    float acc[4][4][4];
    #pragma unroll
    for (int i = 0; i < 4; i++)
        #pragma unroll
        for (int j = 0; j < 4; j++)
            #pragma unroll
            for (int r = 0; r < 4; r++) acc[i][j][r] = 0.f;

    auto load_tile = [&](int buf, int kt) {
        const int k0 = kt * 16;
        #pragma unroll
        for (int i = 0; i < 2; i++) {
            int f = tid + 256 * i;
            int m = f >> 2, kq = (f & 3) << 2;
            unsigned dA = (unsigned)__cvta_generic_to_shared(&As[buf][m][kq]);
            asm volatile("cp.async.cg.shared.global [%0], [%1], 16;"
                         :: "r"(dA), "l"(A + (size_t)(m0 + m) * K + k0 + kq));
            int kb = f >> 5, nq = (f & 31) << 2;
            unsigned dB = (unsigned)__cvta_generic_to_shared(&Bs[buf][kb][nq]);
            asm volatile("cp.async.cg.shared.global [%0], [%1], 16;"
                         :: "r"(dB), "l"(B + (size_t)(k0 + kb) * N + n0 + nq));
        }
    };

    load_tile(0, 0);
    asm volatile("cp.async.commit_group;");
    const int ntiles = K >> 4;
    for (int kt = 0; kt < ntiles; kt++) {
        const int buf = kt & 1;
        if (kt + 1 < ntiles) {
            load_tile(buf ^ 1, kt + 1);
            asm volatile("cp.async.commit_group;");
            asm volatile("cp.async.wait_group 1;");
        } else {
            asm volatile("cp.async.wait_group 0;");
        }
        __syncthreads();
        #pragma unroll
        for (int ks = 0; ks < 16; ks += 8) {
            unsigned bhi[4][2], blo[4][2];
            #pragma unroll
            for (int nt = 0; nt < 4; nt++) {
                int cn = wn + nt * 8 + grp;
                split32(Bs[buf][ks + qid][cn],     bhi[nt][0], blo[nt][0]);
                split32(Bs[buf][ks + qid + 4][cn], bhi[nt][1], blo[nt][1]);
            }
            #pragma unroll
            for (int mt = 0; mt < 4; mt++) {
                unsigned ahi[4], alo[4];
                int rm = wm + mt * 16 + grp;
                split32(As[buf][rm][ks + qid],         ahi[0], alo[0]);
                split32(As[buf][rm + 8][ks + qid],     ahi[1], alo[1]);
                split32(As[buf][rm][ks + qid + 4],     ahi[2], alo[2]);
                split32(As[buf][rm + 8][ks + qid + 4], ahi[3], alo[3]);
                #pragma unroll
                for (int nt = 0; nt < 4; nt++) {
                    MMA8(acc[mt][nt], ahi, bhi[nt]);
                    MMA8(acc[mt][nt], alo, bhi[nt]);
                    MMA8(acc[mt][nt], ahi, blo[nt]);
                }
            }
        }
        __syncthreads();
    }

    #pragma unroll
    for (int mt = 0; mt < 4; mt++) {
        int r0 = m0 + wm + mt * 16 + grp;
        #pragma unroll
        for (int nt = 0; nt < 4; nt++) {
            int c = n0 + wn + nt * 8 + qid * 2;
            float2 bb = *(const float2*)&bias[c];
            float2 v0 = make_float2(acc[mt][nt][0] + bb.x, acc[mt][nt][1] + bb.y);
            float2 v1 = make_float2(acc[mt][nt][2] + bb.x, acc[mt][nt][3] + bb.y);
            if (resid) {
                float2 ra = *(const float2*)&resid[(size_t)r0 * N + c];
                float2 rb = *(const float2*)&resid[(size_t)(r0 + 8) * N + c];
                v0.x += ra.x; v0.y += ra.y; v1.x += rb.x; v1.y += rb.y;
            }
            *(float2*)&C[(size_t)r0 * N + c]       = v0;
            *(float2*)&C[(size_t)(r0 + 8) * N + c] = v1;
        }
    }
}

// ---------------- RoPE (in-place on g_qkv: 32 q-heads + 8 k-heads, contiguous) ----------------
__global__ void rope_kernel(const float* __restrict__ cos_t,
                            const float* __restrict__ sin_t) {
    int t = blockIdx.x;
    const float* c = cos_t + t * 32;
    const float* s = sin_t + t * 32;
    float* rowbase = g_qkv + (size_t)t * QKVD;
    for (int i = threadIdx.x; i < 40 * 32; i += blockDim.x) {
        int head = i >> 5, r = i & 31;
        float* base = rowbase + head * HEADD;
        float x1 = base[r], x2 = base[r + 32];
        float cv = c[r], sv = s[r];
        base[r]      = x1 * cv - x2 * sv;
        base[r + 32] = x2 * cv + x1 * sv;
    }
}

// ---------------- tiled sliding-window GQA attention with sink ----------------
// grid: (64 q-tiles of 32, 8 kv heads), 256 threads.
// K (transposed) + V + Q staged in dynamic smem, shared across the 4 GQA heads.
#define KMAX 160
#define KT_STRIDE 164
#define V_STRIDE 68
#define Q_STRIDE 68
#define S_STRIDE 164
// float offsets in dynamic smem
#define OFF_KT 0
#define OFF_V  (64 * KT_STRIDE)                 // 10496
#define OFF_Q  (OFF_V + KMAX * V_STRIDE)        // 21376
#define OFF_S  (OFF_Q + 32 * Q_STRIDE)          // 23552
#define SMEM_FLOATS (OFF_S + 32 * S_STRIDE)     // 28800 -> 115200 B

__global__ void attn2_kernel(const float* __restrict__ sinks) {
    extern __shared__ float sm[];
    float* KsT = sm + OFF_KT;   // [64][KT_STRIDE]  KsT[d][k]
    float* Vs  = sm + OFF_V;    // [160][V_STRIDE]  Vs[k][d]
    float* Qs  = sm + OFF_Q;    // [32][Q_STRIDE]
    float* S   = sm + OFF_S;    // [32][S_STRIDE]

    const int qt = blockIdx.x;
    const int n  = blockIdx.y;
    const int q0 = qt * 32;
    const int k0 = (q0 - SWIN > 0) ? (q0 - SWIN) : 0;
    const int kcnt = q0 + 32 - k0;      // <= 160
    const int tid = threadIdx.x;
    const int lane = tid & 31, wid = tid >> 5;

    const float* kbase = g_qkv + (size_t)k0 * QKVD + NHEADS * HEADD + n * HEADD;
    const float* vbase = kbase + NKVH * HEADD;

    // stage K (transposed) and V
    for (int f = tid; f < kcnt * 16; f += 256) {
        int r = f >> 4, dq = (f & 15) * 4;
        float4 kv = *(const float4*)(kbase + (size_t)r * QKVD + dq);
        KsT[(dq + 0) * KT_STRIDE + r] = kv.x;
        KsT[(dq + 1) * KT_STRIDE + r] = kv.y;
        KsT[(dq + 2) * KT_STRIDE + r] = kv.z;
        KsT[(dq + 3) * KT_STRIDE + r] = kv.w;
        float4 vv = *(const float4*)(vbase + (size_t)r * QKVD + dq);
        *(float4*)&Vs[r * V_STRIDE + dq] = vv;
    }
    __syncthreads();

    for (int g = 0; g < 4; g++) {
        const int h = n * 4 + g;
        // stage Q for this head
        for (int f = tid; f < 32 * 16; f += 256) {
            int r = f >> 4, dq = (f & 15) * 4;
            *(float4*)&Qs[r * Q_STRIDE + dq] =
                *(const float4*)(g_qkv + (size_t)(q0 + r) * QKVD + h * HEADD + dq);
        }
        __syncthreads();
        const float snk = sinks[h];

        #pragma unroll
        for (int qq = 0; qq < 4; qq++) {
            const int qi = wid * 4 + qq;
            const int qg = q0 + qi;
            const int khi = qg - k0;
            int klo = qg - SWIN - k0; if (klo < 0) klo = 0;
            const float* qrow = Qs + qi * Q_STRIDE;
            float lmax = -INFINITY;

            // pass 1: scores (4 keys per lane-iteration)
            for (int kb = lane; kb < 40; kb += 32) {
                const int kk = kb * 4;
                float s0 = 0.f, s1 = 0.f, s2 = 0.f, s3 = 0.f;
                #pragma unroll
                for (int d = 0; d < 64; d += 4) {
                    float4 q4 = *(const float4*)(qrow + d);
                    float4 kv;
                    kv = *(const float4*)&KsT[(d + 0) * KT_STRIDE + kk];
                    s0 += q4.x * kv.x; s1 += q4.x * kv.y; s2 += q4.x * kv.z; s3 += q4.x * kv.w;
                    kv = *(const float4*)&KsT[(d + 1) * KT_STRIDE + kk];
                    s0 += q4.y * kv.x; s1 += q4.y * kv.y; s2 += q4.y * kv.z; s3 += q4.y * kv.w;
                    kv = *(const float4*)&KsT[(d + 2) * KT_STRIDE + kk];
                    s0 += q4.z * kv.x; s1 += q4.z * kv.y; s2 += q4.z * kv.z; s3 += q4.z * kv.w;
                    kv = *(const float4*)&KsT[(d + 3) * KT_STRIDE + kk];
                    s0 += q4.w * kv.x; s1 += q4.w * kv.y; s2 += q4.w * kv.z; s3 += q4.w * kv.w;
                }
                float v0 = (kk + 0 >= klo && kk + 0 <= khi) ? s0 * 0.125f : -INFINITY;
                float v1 = (kk + 1 >= klo && kk + 1 <= khi) ? s1 * 0.125f : -INFINITY;
                float v2 = (kk + 2 >= klo && kk + 2 <= khi) ? s2 * 0.125f : -INFINITY;
                float v3 = (kk + 3 >= klo && kk + 3 <= khi) ? s3 * 0.125f : -INFINITY;
                *(float4*)&S[qi * S_STRIDE + kk] = make_float4(v0, v1, v2, v3);
                lmax = fmaxf(lmax, fmaxf(fmaxf(v0, v1), fmaxf(v2, v3)));
            }
            #pragma unroll
            for (int o = 16; o; o >>= 1)
                lmax = fmaxf(lmax, __shfl_xor_sync(0xffffffffu, lmax, o));
            lmax = fmaxf(lmax, snk);

            // pass 2: exp + sum
            float lsum = 0.f;
            for (int k = lane; k < KMAX; k += 32) {
                float e = expf(S[qi * S_STRIDE + k] - lmax);
                S[qi * S_STRIDE + k] = e;
                lsum += e;
            }
            #pragma unroll
            for (int o = 16; o; o >>= 1)
                lsum += __shfl_xor_sync(0xffffffffu, lsum, o);
            const float inv = 1.f / (lsum + expf(snk - lmax));

            // pass 3: V accumulate (lanes over head dim)
            float a0 = 0.f, a1 = 0.f;
            const int d0 = lane, d1 = lane + 32;
            #pragma unroll 4
            for (int k = 0; k < kcnt; k++) {
                float p = S[qi * S_STRIDE + k];
                a0 += p * Vs[k * V_STRIDE + d0];
                a1 += p * Vs[k * V_STRIDE + d1];
            }
            g_attn[(size_t)qg * HDIM + h * HEADD + d0] = a0 * inv;
            g_attn[(size_t)qg * HDIM + h * HEADD + d1] = a1 * inv;
        }
        __syncthreads();
    }
}

// ---------------- launch ----------------
extern "C" void kernel_launch(void* const* d_in, const int* in_sizes, int n_in,
                              void* d_out, int out_size) {
    const float* x          = (const float*)d_in[0];
    const float* scale      = (const float*)d_in[1];
    const float* sinks      = (const float*)d_in[2];
    const float* qkv_kernel = (const float*)d_in[3];
    const float* qkv_bias   = (const float*)d_in[4];
    const float* out_kernel = (const float*)d_in[5];
    const float* out_bias   = (const float*)d_in[6];
    const float* cos_t      = (const float*)d_in[7];
    const float* sin_t      = (const float*)d_in[8];
    // d_in[9] = mask: unused (sliding window applied structurally)
    float* out = (float*)d_out;

    void *p_normed = nullptr, *p_qkv = nullptr, *p_attn = nullptr;
    cudaGetSymbolAddress(&p_normed, g_normed);
    cudaGetSymbolAddress(&p_qkv, g_qkv);
    cudaGetSymbolAddress(&p_attn, g_attn);

    static bool attr_set = false;
    if (!attr_set) {
        cudaFuncSetAttribute(attn2_kernel,
                             cudaFuncAttributeMaxDynamicSharedMemorySize,
                             SMEM_FLOATS * 4);
        attr_set = true;
    }

    rmsnorm_kernel<<<TT, 256>>>(x, scale);

    // QKV: [2048,2048] @ [2048,3072]
    gemm_tf32<<<dim3(QKVD / 128, TT / 128), 256>>>(
        (const float*)p_normed, qkv_kernel, qkv_bias, nullptr,
        (float*)p_qkv, QKVD, HDIM);

    rope_kernel<<<TT, 256>>>(cos_t, sin_t);

    attn2_kernel<<<dim3(TT / 32, NKVH), 256, SMEM_FLOATS * 4>>>(sinks);

    // out-proj + residual: [2048,2048] @ [2048,2048] + x
    gemm_tf32<<<dim3(HDIM / 128, TT / 128), 256>>>(
        (const float*)p_attn, out_kernel, out_bias, x,
        out, HDIM, HDIM);
}